// round 6
// baseline (speedup 1.0000x reference)
#include <cuda_runtime.h>
#include <math.h>
#include <stdint.h>

// ---------------- constants ----------------
#define NBF   148         // fused kernel blocks (1/SM, all co-resident)
#define NBC   64          // compute CTAs (512 warps)
#define NAUX  (NBF - NBC) // 84 aux CTAs
#define NT1   256
#define NBD   3125        // decoder: 3125 blocks * 8 warps * 2 rows = 50000
#define NTD   256

#define HC    256
#define HW    512
#define VOC   50000
#define LCH   12

// d_out layout: [y(50000) | h_word_h(1024) | h_word_c(1024) | h_char_h(512) | h_char_c(512)]
#define OUT_WH  50000
#define OUT_WC  51024
#define OUT_CH  52048
#define OUT_CC  52560

// ---------------- dataflow flags (one 128B line each) ----------------
#define F_H0    0     // +p : char layer0 state p complete (256 sigs)
#define F_H1    13    // +p : char layer1 state p complete (256 sigs)
#define F_PX    26    // +t : layer0 x-partials for step t done (1024 sigs)
#define F_XC    38    // xc rows done (512)
#define F_GATE  39    // gate done (1)
#define F_HP0   40    // word layer0 h-partials done (2048)
#define F_HP1   41    // word layer1 h-partials done (2048)
#define F_WIHE  42    // Wih_l0 . word_emb rows done (2048)
#define F_W0    43    // word layer0 elements done (512)
#define NFLAGS  45
__device__ unsigned g_flags[NFLAGS * 32];

// ---------------- device-global scratch ----------------
__device__ float g_h0[4][HC];         // char layer0 state ring
__device__ float g_h1[4][HC];         // char layer1 state ring
__device__ float g_c1[HC];
__device__ float g_px[LCH * 1024];    // layer0: Wih@x_t + biases
__device__ float g_xc[HW];
__device__ float g_gate;
__device__ float g_wihe[2048];        // word l0: Wih@word_emb[widx]
__device__ float g_hp[2 * 2048];      // word: Whh@h_prev + biases
__device__ float g_wh[HW];
__device__ float g_y[HW];
__device__ float g_sink;

// ---------------- helpers ----------------
__device__ __forceinline__ void sig(int idx) {
    asm volatile("red.release.gpu.add.u32 [%0], %1;"
                 :: "l"(&g_flags[idx * 32]), "r"(1u) : "memory");
}
__device__ __forceinline__ void sig8(int idx) {
    asm volatile("red.release.gpu.add.u32 [%0], %1;"
                 :: "l"(&g_flags[idx * 32]), "r"(8u) : "memory");
}
__device__ __forceinline__ unsigned ldacq(int idx) {
    unsigned v;
    asm volatile("ld.acquire.gpu.u32 %0, [%1];"
                 : "=r"(v) : "l"(&g_flags[idx * 32]) : "memory");
    return v;
}
__device__ __forceinline__ void waitf(int idx, unsigned tgt) {      // hot spin
    while (ldacq(idx) < tgt) { }
}
__device__ __forceinline__ void waitf_slow(int idx, unsigned tgt) { // backoff spin
    while (ldacq(idx) < tgt) __nanosleep(128);
}
__device__ __forceinline__ float warp_sum(float v) {
#pragma unroll
    for (int o = 16; o > 0; o >>= 1) v += __shfl_xor_sync(0xffffffffu, v, o);
    return v;
}
__device__ __forceinline__ float fsig(float x)  { return __fdividef(1.f, 1.f + __expf(-x)); }
__device__ __forceinline__ float ftanh(float x) { float e = __expf(2.f * x); return 1.f - __fdividef(2.f, e + 1.f); }
__device__ __forceinline__ float dot4(float4 a, float4 b) {
    return a.x * b.x + a.y * b.y + a.z * b.z + a.w * b.w;
}

// ============ fused kernel ============
__global__ void __launch_bounds__(NT1, 1) k_fused(
    const int*   x_word,   const int*   x_char,
    const float* h_word_h, const float* h_word_c,
    const float* h_char_h, const float* h_char_c,
    const float* word_emb, const float* word_Wih, const float* word_Whh,
    const float* word_bih, const float* word_bhh,
    const float* char_emb, const float* char_Wih, const float* char_Whh,
    const float* char_bih, const float* char_bhh,
    const float* c2e,      const float* gw_vec,   const float* gb_scal,
    float* out)
{
    const int lane = threadIdx.x & 31;
    const int wid  = threadIdx.x >> 5;

    // ================= aux CTAs =================
    if (blockIdx.x >= NBC) {
        const int ab    = blockIdx.x - NBC;            // 0..83
        const int awarp = ab * (NT1 / 32) + wid;       // 0..671
        const int NWRP  = NAUX * (NT1 / 32);           // 672

        __shared__ int sxa[LCH];
        if (threadIdx.x < LCH) sxa[threadIdx.x] = x_char[threadIdx.x];
        __syncthreads();

        // gate (aux CTA 0, warp 0) — fully independent
        if (ab == 0 && wid == 0) {
            const int widx = x_word[0];
            const float4* we = (const float4*)(word_emb + (size_t)widx * HW);
            const float4* gp = (const float4*)gw_vec;
            float s = 0.f;
#pragma unroll
            for (int u = 0; u < 4; u++) s += dot4(gp[lane + 32 * u], we[lane + 32 * u]);
            s = warp_sum(s) + gb_scal[0];
            if (lane == 0) { __stcg(&g_gate, fmaxf(s, 0.f)); sig(F_GATE); }
        }

        // px: warp owns char_Wih l0 row r (weights cached in regs), produces ALL 12 t's.
        // Total weight traffic: 1 MB (was 12 MB).
        for (int r = awarp; r < 1024; r += NWRP) {
            const float4* w = (const float4*)(char_Wih + (size_t)r * HC);
            const float4 w0 = w[lane], w1 = w[lane + 32];
            const float  b  = char_bih[r] + char_bhh[r];
            float vals[LCH];
#pragma unroll
            for (int t = 0; t < LCH; t++) {
                const float4* xe = (const float4*)(char_emb + (size_t)sxa[t] * HC);
                vals[t] = dot4(w0, xe[lane]) + dot4(w1, xe[lane + 32]);
            }
#pragma unroll
            for (int t = 0; t < LCH; t++) {
                const float a = warp_sum(vals[t]);
                if (lane == 0) { __stcg(&g_px[t * 1024 + r], a + b); sig(F_PX + t); }
            }
        }

        // tiny warm: c2e (0.5MB) + h_word_c — needed at char end, cheap now
        {
            float s = 0.f;
            const float4* cb = (const float4*)c2e;
            for (int i = ab * NT1 + threadIdx.x; i < HW * HC / 4; i += NAUX * NT1) {
                const float4 v = __ldcg(cb + i);
                s += v.x + v.w;
            }
            const int i2 = ab * NT1 + threadIdx.x;
            if (i2 < 2 * HW / 4) { const float4 v = __ldcg(((const float4*)h_word_c) + i2); s += v.y; }
            if (s == 1.25e33f) g_sink = s;
        }

        // ---- QUIET PERIOD: no bulk streaming while the char chain runs ----
        if (threadIdx.x == 0) waitf_slow(F_H0 + (LCH - 3), HC);
        __syncthreads();

        // wihe (2048 rows) + hp layer0 (2048 rows), interleaved; then hp layer1
        const int widx = x_word[0];
        const float4* we = (const float4*)(word_emb + (size_t)widx * HW);
        float4 ev[4];
#pragma unroll
        for (int u = 0; u < 4; u++) ev[u] = we[lane + 32 * u];

        for (int r = awarp; r < 4096; r += NWRP) {
            if (r < 2048) {                       // wihe row r
                const float4* w = (const float4*)(word_Wih + (size_t)r * HW);
                float a = 0.f;
#pragma unroll
                for (int u = 0; u < 4; u++) a += dot4(w[lane + 32 * u], ev[u]);
                a = warp_sum(a);
                if (lane == 0) { __stcg(&g_wihe[r], a); sig(F_WIHE); }
            } else {                              // hp layer0 row r-2048
                const int rr = r - 2048;
                const float4* w  = (const float4*)(word_Whh + (size_t)rr * HW);
                const float4* hv = (const float4*)h_word_h;
                float a = 0.f;
#pragma unroll
                for (int u = 0; u < 4; u++) a += dot4(w[lane + 32 * u], hv[lane + 32 * u]);
                a = warp_sum(a);
                if (lane == 0) {
                    __stcg(&g_hp[rr], a + word_bih[rr] + word_bhh[rr]);
                    sig(F_HP0);
                }
            }
        }
        for (int r = awarp + 2048; r < 4096; r += NWRP) {   // hp layer1
            const float4* w  = (const float4*)(word_Whh + (size_t)r * HW);
            const float4* hv = (const float4*)(h_word_h + HW);
            float a = 0.f;
#pragma unroll
            for (int u = 0; u < 4; u++) a += dot4(w[lane + 32 * u], hv[lane + 32 * u]);
            a = warp_sum(a);
            if (lane == 0) {
                __stcg(&g_hp[r], a + word_bih[r] + word_bhh[r]);
                sig(F_HP1);
            }
        }
        return;
    }

    // ================= compute CTAs (0..63) =================
    // CTAs 0..31 -> char layer0 (gw 0..255); CTAs 32..63 -> char layer1
    const int gw    = blockIdx.x * (NT1 / 32) + wid;   // 0..511
    const int layer = (gw >= HC) ? 1 : 0;
    const int j     = layer ? (gw - HC) : gw;

    float c = h_char_c[layer * HC + j];

    // seed state 0 (CTA-aggregated signal)
    if (lane == 0) {
        const float h0v = h_char_h[layer * HC + j];
        if (layer == 0) __stcg(&g_h0[0][j], h0v);
        else            __stcg(&g_h1[0][j], h0v);
    }
    __syncthreads();
    if (threadIdx.x == 0) sig8(layer == 0 ? (F_H0 + 0) : (F_H1 + 0));

    if (layer == 0) {
        // ---- layer 0: Whh only in regs; Wih@x+bias precomputed in px ----
        float4 wh[4][2];
#pragma unroll
        for (int q = 0; q < 4; q++) {
            const float4* ph = (const float4*)(char_Whh + (size_t)(q * HC + j) * HC);
            wh[q][0] = ph[lane];
            wh[q][1] = ph[lane + 32];
        }
#pragma unroll 1
        for (int t = 0; t < LCH; t++) {
            waitf(F_PX + t, 1024);
            float px[4];
#pragma unroll
            for (int q = 0; q < 4; q++) px[q] = __ldcg(&g_px[t * 1024 + q * HC + j]);
            waitf(F_H0 + t, HC);
            if (t >= 4) waitf(F_H1 + (t - 3), HC);          // WAR guard on ring
            const float4* hb = (const float4*)g_h0[t & 3];
            const float4 h0 = __ldcg(hb + lane), h1 = __ldcg(hb + lane + 32);
            float acc[4];
#pragma unroll
            for (int q = 0; q < 4; q++)
                acc[q] = warp_sum(dot4(wh[q][0], h0) + dot4(wh[q][1], h1)) + px[q];
            const float ig = fsig(acc[0]), fg = fsig(acc[1]);
            const float gg = ftanh(acc[2]), og = fsig(acc[3]);
            c = fg * c + ig * gg;
            const float h = og * ftanh(c);
            if (lane == 0) {
                __stcg(&g_h0[(t + 1) & 3][j], h);
                if (t == LCH - 1) { out[OUT_CH + j] = h; out[OUT_CC + j] = c; }
            }
            __syncthreads();
            if (threadIdx.x == 0) sig8(F_H0 + t + 1);
        }
    } else {
        // ---- layer 1: full Wih+Whh in regs ----
        float4 wi[4][2], wh[4][2];
        float  bias[4];
#pragma unroll
        for (int q = 0; q < 4; q++) {
            const int row = 4 * HC + q * HC + j;
            const float4* pi = (const float4*)(char_Wih + (size_t)row * HC);
            const float4* ph = (const float4*)(char_Whh + (size_t)row * HC);
            wi[q][0] = pi[lane];      wi[q][1] = pi[lane + 32];
            wh[q][0] = ph[lane];      wh[q][1] = ph[lane + 32];
            bias[q]  = char_bih[row] + char_bhh[row];
        }
#pragma unroll 1
        for (int t = 0; t < LCH; t++) {
            waitf(F_H0 + t + 1, HC);     // x input: layer0 state t+1
            waitf(F_H1 + t, HC);         // own state t
            const float4* xb = (const float4*)g_h0[(t + 1) & 3];
            const float4* hb = (const float4*)g_h1[t & 3];
            const float4 x0 = __ldcg(xb + lane), x1 = __ldcg(xb + lane + 32);
            const float4 h0 = __ldcg(hb + lane), h1 = __ldcg(hb + lane + 32);
            float acc[4];
#pragma unroll
            for (int q = 0; q < 4; q++) {
                float a = dot4(wi[q][0], x0) + dot4(wi[q][1], x1)
                        + dot4(wh[q][0], h0) + dot4(wh[q][1], h1);
                acc[q] = warp_sum(a) + bias[q];
            }
            const float ig = fsig(acc[0]), fg = fsig(acc[1]);
            const float gg = ftanh(acc[2]), og = fsig(acc[3]);
            c = fg * c + ig * gg;
            const float h = og * ftanh(c);
            if (lane == 0) {
                __stcg(&g_h1[(t + 1) & 3][j], h);
                if (t == LCH - 1) {
                    __stcg(&g_c1[j], c);
                    out[OUT_CH + HC + j] = h;
                    out[OUT_CC + HC + j] = c;
                }
            }
            __syncthreads();
            if (threadIdx.x == 0) sig8(F_H1 + t + 1);
        }
    }

    // ---------------- xc = c2e @ c1 (warp gw -> row gw) ----------------
    {
        waitf(F_H1 + LCH, HC);
        const float4* pr  = (const float4*)(c2e + (size_t)gw * HC);
        const float4* c1b = (const float4*)g_c1;
        float a = dot4(pr[lane],      __ldcg(c1b + lane))
                + dot4(pr[lane + 32], __ldcg(c1b + lane + 32));
        a = warp_sum(a);
        if (lane == 0) __stcg(&g_xc[gw], a);
        __syncthreads();
        if (threadIdx.x == 0) sig8(F_XC);
    }

    // ---------------- word LSTM layer 0 (warp gw -> element gw) ----------------
    const int e = gw;
    {
        waitf(F_XC, HW);
        waitf(F_GATE, 1);
        waitf_slow(F_WIHE, 2048);
        waitf_slow(F_HP0, 2048);
        const float gv = __ldcg(&g_gate);
        const float4* xc = (const float4*)g_xc;
        float4 xv[4];
#pragma unroll
        for (int u = 0; u < 4; u++) xv[u] = __ldcg(xc + lane + 32 * u);
        float acc[4];
#pragma unroll
        for (int q = 0; q < 4; q++) {
            const int row = q * HW + e;
            const float4* pwi = (const float4*)(word_Wih + (size_t)row * HW);
            float a = 0.f;
#pragma unroll
            for (int u = 0; u < 4; u++) a += dot4(__ldcg(pwi + lane + 32 * u), xv[u]);
            acc[q] = gv * warp_sum(a) + (1.f - gv) * __ldcg(&g_wihe[row]) + __ldcg(&g_hp[row]);
        }
        const float ig = fsig(acc[0]), fg = fsig(acc[1]);
        const float gg = ftanh(acc[2]), og = fsig(acc[3]);
        const float cw = fg * h_word_c[e] + ig * gg;
        const float hw = og * ftanh(cw);
        if (lane == 0) {
            __stcg(&g_wh[e], hw);
            out[OUT_WH + e] = hw;
            out[OUT_WC + e] = cw;
        }
        __syncthreads();
        if (threadIdx.x == 0) sig8(F_W0);
    }

    // ---------------- word LSTM layer 1 ----------------
    {
        waitf_slow(F_HP1, 2048);
        waitf(F_W0, HW);
        const float4* xb = (const float4*)g_wh;
        float4 xv[4];
#pragma unroll
        for (int u = 0; u < 4; u++) xv[u] = __ldcg(xb + lane + 32 * u);
        float acc[4];
#pragma unroll
        for (int q = 0; q < 4; q++) {
            const int row = 2048 + q * HW + e;
            const float4* pwi = (const float4*)(word_Wih + (size_t)row * HW);
            float a = 0.f;
#pragma unroll
            for (int u = 0; u < 4; u++) a += dot4(__ldcg(pwi + lane + 32 * u), xv[u]);
            acc[q] = warp_sum(a) + __ldcg(&g_hp[row]);
        }
        const float ig = fsig(acc[0]), fg = fsig(acc[1]);
        const float gg = ftanh(acc[2]), og = fsig(acc[3]);
        const float cw = fg * h_word_c[HW + e] + ig * gg;
        const float hw = og * ftanh(cw);
        if (lane == 0) {
            __stcg(&g_y[e], hw);
            out[OUT_WH + HW + e] = hw;
            out[OUT_WC + HW + e] = cw;
        }
    }
}

// ============ decoder GEMV (50000 x 512), 2 rows/warp, streaming loads ============
__global__ void __launch_bounds__(NTD) k_dec(const float* __restrict__ dec_W,
                                             const float* __restrict__ dec_b,
                                             float* __restrict__ out)
{
    // reset dataflow flags for the next graph replay (k_fused already done)
    if (blockIdx.x == 0) {
        for (int i = threadIdx.x; i < NFLAGS * 32; i += NTD) g_flags[i] = 0;
    }

    __shared__ float ys[HW];
    for (int i = threadIdx.x; i < HW; i += NTD) ys[i] = __ldcg(&g_y[i]);
    __syncthreads();

    const int lane = threadIdx.x & 31;
    const int wid  = threadIdx.x >> 5;
    const int gw   = blockIdx.x * (NTD / 32) + wid;
    const int r0   = 2 * gw;                        // 25000 warps * 2 rows

    const float4* y4 = (const float4*)ys;
    float4 yv[4];
#pragma unroll
    for (int u = 0; u < 4; u++) yv[u] = y4[lane + 32 * u];

    const float4* w0 = (const float4*)(dec_W + (size_t)r0 * HW);
    const float4* w1 = w0 + HW / 4;
    float a0 = 0.f, a1 = 0.f;
#pragma unroll
    for (int u = 0; u < 4; u++) {
        const float4 v0 = __ldcs(w0 + lane + 32 * u);   // evict-first: protect L2
        const float4 v1 = __ldcs(w1 + lane + 32 * u);
        a0 += dot4(v0, yv[u]);
        a1 += dot4(v1, yv[u]);
    }
    a0 = warp_sum(a0);
    a1 = warp_sum(a1);
    if (lane == 0) {
        out[r0]     = a0 + dec_b[r0];
        out[r0 + 1] = a1 + dec_b[r0 + 1];
    }
}

// ---------------- launch ----------------
extern "C" void kernel_launch(void* const* d_in, const int* in_sizes, int n_in,
                              void* d_out, int out_size)
{
    (void)in_sizes; (void)n_in; (void)out_size;
    const int*   x_word   = (const int*)  d_in[0];
    const int*   x_char   = (const int*)  d_in[1];
    const float* h_word_h = (const float*)d_in[2];
    const float* h_word_c = (const float*)d_in[3];
    const float* h_char_h = (const float*)d_in[4];
    const float* h_char_c = (const float*)d_in[5];
    const float* word_emb = (const float*)d_in[6];
    const float* word_Wih = (const float*)d_in[7];
    const float* word_Whh = (const float*)d_in[8];
    const float* word_bih = (const float*)d_in[9];
    const float* word_bhh = (const float*)d_in[10];
    const float* dec_W    = (const float*)d_in[11];
    const float* dec_b    = (const float*)d_in[12];
    const float* char_emb = (const float*)d_in[13];
    const float* char_Wih = (const float*)d_in[14];
    const float* char_Whh = (const float*)d_in[15];
    const float* char_bih = (const float*)d_in[16];
    const float* char_bhh = (const float*)d_in[17];
    const float* c2e      = (const float*)d_in[18];
    const float* g_w      = (const float*)d_in[19];
    const float* g_b      = (const float*)d_in[20];
    float* out = (float*)d_out;

    k_fused<<<NBF, NT1>>>(x_word, x_char, h_word_h, h_word_c, h_char_h, h_char_c,
                          word_emb, word_Wih, word_Whh, word_bih, word_bhh,
                          char_emb, char_Wih, char_Whh, char_bih, char_bhh,
                          c2e, g_w, g_b, out);
    k_dec<<<NBD, NTD>>>(dec_W, dec_b, out);
}

// round 7
// speedup vs baseline: 1.0293x; 1.0293x over previous
#include <cuda_runtime.h>
#include <math.h>
#include <stdint.h>

// ---------------- constants ----------------
#define NBF   148         // fused kernel blocks (1/SM, all co-resident)
#define NBC   64          // compute CTAs (512 warps)
#define NAUX  (NBF - NBC) // 84 aux CTAs
#define NT1   256
#define NBD   3125        // decoder: 3125 blocks * 8 warps * 2 rows = 50000
#define NTD   256

#define HC    256
#define HW    512
#define VOC   50000
#define LCH   12

// d_out layout: [y(50000) | h_word_h(1024) | h_word_c(1024) | h_char_h(512) | h_char_c(512)]
#define OUT_WH  50000
#define OUT_WC  51024
#define OUT_CH  52048
#define OUT_CC  52560

// ---------------- dataflow flags (one 128B line each) ----------------
#define F_H0    0     // +p : char layer0 state p complete (target 256)
#define F_H1    13    // +p : char layer1 state p complete (target 256)
#define F_PX    26    // +t : layer0 x-partials step t (target 1024, <=84 atomics)
#define F_XC    38    // xc rows (target 512)
#define F_GATE  39    // gate (target 1)
#define F_HP0   40    // word l0 h-partials (target 2048, <=84 atomics)
#define F_HP1   41    // word l1 h-partials (target 2048, <=84 atomics)
#define F_WIHE  42    // Wih_l0 . word_emb (target 2048, <=84 atomics)
#define F_W0    43    // word l0 elements (target 512)
#define NFLAGS  45
__device__ unsigned g_flags[NFLAGS * 32];

// ---------------- device-global scratch ----------------
__device__ float g_h0[4][HC];         // char layer0 state ring
__device__ float g_h1[4][HC];         // char layer1 state ring
__device__ float g_c1[HC];
__device__ float g_px[LCH * 1024];    // layer0: Wih@x_t + biases
__device__ float g_xc[HW];
__device__ float g_gate;
__device__ float g_wihe[2048];        // word l0: Wih@word_emb[widx]
__device__ float g_hp[2 * 2048];      // word: Whh@h_prev + biases
__device__ float g_wh[HW];
__device__ float g_y[HW];
__device__ float g_sink;

// ---------------- helpers ----------------
__device__ __forceinline__ void sign(int idx, unsigned n) {
    asm volatile("red.release.gpu.add.u32 [%0], %1;"
                 :: "l"(&g_flags[idx * 32]), "r"(n) : "memory");
}
__device__ __forceinline__ unsigned ldacq(int idx) {
    unsigned v;
    asm volatile("ld.acquire.gpu.u32 %0, [%1];"
                 : "=r"(v) : "l"(&g_flags[idx * 32]) : "memory");
    return v;
}
__device__ __forceinline__ float warp_sum(float v) {
#pragma unroll
    for (int o = 16; o > 0; o >>= 1) v += __shfl_xor_sync(0xffffffffu, v, o);
    return v;
}
__device__ __forceinline__ float fsig(float x)  { return __fdividef(1.f, 1.f + __expf(-x)); }
__device__ __forceinline__ float ftanh(float x) { float e = __expf(2.f * x); return 1.f - __fdividef(2.f, e + 1.f); }
__device__ __forceinline__ float dot4(float4 a, float4 b) {
    return a.x * b.x + a.y * b.y + a.z * b.z + a.w * b.w;
}
__device__ __forceinline__ int imax(int a, int b) { return a > b ? a : b; }
__device__ __forceinline__ int imin(int a, int b) { return a < b ? a : b; }

// ============ fused kernel ============
__global__ void __launch_bounds__(NT1, 1) k_fused(
    const int*   x_word,   const int*   x_char,
    const float* h_word_h, const float* h_word_c,
    const float* h_char_h, const float* h_char_c,
    const float* word_emb, const float* word_Wih, const float* word_Whh,
    const float* word_bih, const float* word_bhh,
    const float* char_emb, const float* char_Wih, const float* char_Whh,
    const float* char_bih, const float* char_bhh,
    const float* c2e,      const float* gw_vec,   const float* gb_scal,
    float* out)
{
    const int lane = threadIdx.x & 31;
    const int wid  = threadIdx.x >> 5;

    // ================= aux CTAs =================
    if (blockIdx.x >= NBC) {
        const int ab = blockIdx.x - NBC;            // 0..83

        __shared__ int sxa[LCH];
        if (threadIdx.x < LCH) sxa[threadIdx.x] = x_char[threadIdx.x];
        __syncthreads();

        // gate — CTA 83 (px-idle) warp 0, fully independent
        if (ab == 83 && wid == 0) {
            const int widx = x_word[0];
            const float4* we = (const float4*)(word_emb + (size_t)widx * HW);
            const float4* gp = (const float4*)gw_vec;
            float s = 0.f;
#pragma unroll
            for (int u = 0; u < 4; u++) s += dot4(gp[lane + 32 * u], we[lane + 32 * u]);
            s = warp_sum(s) + gb_scal[0];
            if (lane == 0) { __stcg(&g_gate, fmaxf(s, 0.f)); sign(F_GATE, 1); }
        }

        // ---- stage 1: px, CTA-chunked (13 rows/CTA), ONE aggregated sig per t ----
        {
            const int r0c = imin(ab * 13, 1024);
            const int r1c = imin(r0c + 13, 1024);
            for (int r = r0c + wid; r < r1c; r += 8) {
                const float4* w = (const float4*)(char_Wih + (size_t)r * HC);
                const float4 w0 = w[lane], w1 = w[lane + 32];
                const float  b  = char_bih[r] + char_bhh[r];
                float vals[LCH];
#pragma unroll
                for (int t = 0; t < LCH; t++) {
                    const float4* xe = (const float4*)(char_emb + (size_t)sxa[t] * HC);
                    vals[t] = dot4(w0, xe[lane]) + dot4(w1, xe[lane + 32]);
                }
#pragma unroll
                for (int t = 0; t < LCH; t++) {
                    const float a = warp_sum(vals[t]);
                    if (lane == 0) __stcg(&g_px[t * 1024 + r], a + b);
                }
            }
            __syncthreads();
            if (threadIdx.x == 0 && r1c > r0c) {
                const unsigned n = (unsigned)(r1c - r0c);
#pragma unroll
                for (int t = 0; t < LCH; t++) sign(F_PX + t, n);
            }
        }

        // ---- stage 2: wihe(2048) + hp0(2048) + hp1(2048), CTA-chunked ----
        {
            const int z0 = imin(ab * 74, 6144);
            const int z1 = imin(z0 + 74, 6144);
            const int widx = x_word[0];
            const float4* we = (const float4*)(word_emb + (size_t)widx * HW);
            float4 ev[4];
#pragma unroll
            for (int u = 0; u < 4; u++) ev[u] = we[lane + 32 * u];

            for (int z = z0 + wid; z < z1; z += 8) {
                if (z < 2048) {                          // wihe row z
                    const float4* w = (const float4*)(word_Wih + (size_t)z * HW);
                    float a = 0.f;
#pragma unroll
                    for (int u = 0; u < 4; u++) a += dot4(w[lane + 32 * u], ev[u]);
                    a = warp_sum(a);
                    if (lane == 0) __stcg(&g_wihe[z], a);
                } else if (z < 4096) {                   // hp layer0 row z-2048
                    const int rr = z - 2048;
                    const float4* w  = (const float4*)(word_Whh + (size_t)rr * HW);
                    const float4* hv = (const float4*)h_word_h;
                    float a = 0.f;
#pragma unroll
                    for (int u = 0; u < 4; u++) a += dot4(w[lane + 32 * u], hv[lane + 32 * u]);
                    a = warp_sum(a);
                    if (lane == 0) __stcg(&g_hp[rr], a + word_bih[rr] + word_bhh[rr]);
                } else {                                 // hp layer1 row z-4096 (+2048)
                    const int row = z - 2048;            // 2048..4095
                    const float4* w  = (const float4*)(word_Whh + (size_t)row * HW);
                    const float4* hv = (const float4*)(h_word_h + HW);
                    float a = 0.f;
#pragma unroll
                    for (int u = 0; u < 4; u++) a += dot4(w[lane + 32 * u], hv[lane + 32 * u]);
                    a = warp_sum(a);
                    if (lane == 0) __stcg(&g_hp[row], a + word_bih[row] + word_bhh[row]);
                }
            }
            __syncthreads();
            if (threadIdx.x == 0 && z1 > z0) {
                const int c0 = imax(0, imin(z1, 2048) - imin(z0, 2048));
                const int c1 = imax(0, imin(z1, 4096) - imax(z0, 2048));
                const int c2 = imax(0, z1 - imax(z0, 4096));
                if (c0) sign(F_WIHE, (unsigned)c0);
                if (c1) sign(F_HP0,  (unsigned)c1);
                if (c2) sign(F_HP1,  (unsigned)c2);
            }
        }

        // tiny warm: keep c2e resident for the xc phase
        {
            float s = 0.f;
            const float4* cb = (const float4*)c2e;
            for (int i = ab * NT1 + threadIdx.x; i < HW * HC / 4; i += NAUX * NT1) {
                const float4 v = __ldcg(cb + i);
                s += v.x + v.w;
            }
            if (s == 1.25e33f) g_sink = s;
        }
        return;
    }

    // ================= compute CTAs (0..63) =================
    const int gw    = blockIdx.x * (NT1 / 32) + wid;   // 0..511
    const int layer = (gw >= HC) ? 1 : 0;
    const int j     = layer ? (gw - HC) : gw;

    float c = h_char_c[layer * HC + j];

    // seed state 0 (CTA-aggregated signal)
    if (lane == 0) {
        const float h0v = h_char_h[layer * HC + j];
        if (layer == 0) __stcg(&g_h0[0][j], h0v);
        else            __stcg(&g_h1[0][j], h0v);
    }
    __syncthreads();
    if (threadIdx.x == 0) sign(layer == 0 ? (F_H0 + 0) : (F_H1 + 0), 8);

    if (layer == 0) {
        // ---- layer 0: Whh in regs; Wih@x+bias precomputed in px ----
        float4 wh[4][2];
#pragma unroll
        for (int q = 0; q < 4; q++) {
            const float4* ph = (const float4*)(char_Whh + (size_t)(q * HC + j) * HC);
            wh[q][0] = ph[lane];
            wh[q][1] = ph[lane + 32];
        }
#pragma unroll 1
        for (int t = 0; t < LCH; t++) {
            // fused poll: px[t], h0(t), WAR guard on ring (h1(t-3) when t>=4)
            const int      gf = (t >= 4) ? (F_H1 + t - 3) : F_H1;
            const unsigned gt = (t >= 4) ? (unsigned)HC : 0u;
            while ((unsigned)(ldacq(F_PX + t) < 1024u) |
                   (unsigned)(ldacq(F_H0 + t) < (unsigned)HC) |
                   (unsigned)(ldacq(gf) < gt)) { }
            float px[4];
#pragma unroll
            for (int q = 0; q < 4; q++) px[q] = __ldcg(&g_px[t * 1024 + q * HC + j]);
            const float4* hb = (const float4*)g_h0[t & 3];
            const float4 h0 = __ldcg(hb + lane), h1 = __ldcg(hb + lane + 32);
            float acc[4];
#pragma unroll
            for (int q = 0; q < 4; q++)
                acc[q] = warp_sum(dot4(wh[q][0], h0) + dot4(wh[q][1], h1)) + px[q];
            const float ig = fsig(acc[0]), fg = fsig(acc[1]);
            const float gg = ftanh(acc[2]), og = fsig(acc[3]);
            c = fg * c + ig * gg;
            const float h = og * ftanh(c);
            if (lane == 0) {
                __stcg(&g_h0[(t + 1) & 3][j], h);
                if (t == LCH - 1) { out[OUT_CH + j] = h; out[OUT_CC + j] = c; }
            }
            __syncthreads();
            if (threadIdx.x == 0) sign(F_H0 + t + 1, 8);
        }
    } else {
        // ---- layer 1: full Wih+Whh in regs ----
        float4 wi[4][2], wh[4][2];
        float  bias[4];
#pragma unroll
        for (int q = 0; q < 4; q++) {
            const int row = 4 * HC + q * HC + j;
            const float4* pi = (const float4*)(char_Wih + (size_t)row * HC);
            const float4* ph = (const float4*)(char_Whh + (size_t)row * HC);
            wi[q][0] = pi[lane];      wi[q][1] = pi[lane + 32];
            wh[q][0] = ph[lane];      wh[q][1] = ph[lane + 32];
            bias[q]  = char_bih[row] + char_bhh[row];
        }
#pragma unroll 1
        for (int t = 0; t < LCH; t++) {
            // fused poll: x = h0(t+1), own h1(t)
            while ((unsigned)(ldacq(F_H0 + t + 1) < (unsigned)HC) |
                   (unsigned)(ldacq(F_H1 + t)     < (unsigned)HC)) { }
            const float4* xb = (const float4*)g_h0[(t + 1) & 3];
            const float4* hb = (const float4*)g_h1[t & 3];
            const float4 x0 = __ldcg(xb + lane), x1 = __ldcg(xb + lane + 32);
            const float4 h0 = __ldcg(hb + lane), h1 = __ldcg(hb + lane + 32);
            float acc[4];
#pragma unroll
            for (int q = 0; q < 4; q++) {
                float a = dot4(wi[q][0], x0) + dot4(wi[q][1], x1)
                        + dot4(wh[q][0], h0) + dot4(wh[q][1], h1);
                acc[q] = warp_sum(a) + bias[q];
            }
            const float ig = fsig(acc[0]), fg = fsig(acc[1]);
            const float gg = ftanh(acc[2]), og = fsig(acc[3]);
            c = fg * c + ig * gg;
            const float h = og * ftanh(c);
            if (lane == 0) {
                __stcg(&g_h1[(t + 1) & 3][j], h);
                if (t == LCH - 1) {
                    __stcg(&g_c1[j], c);
                    out[OUT_CH + HC + j] = h;
                    out[OUT_CC + HC + j] = c;
                }
            }
            __syncthreads();
            if (threadIdx.x == 0) sign(F_H1 + t + 1, 8);
        }
    }

    // ---------------- xc = c2e @ c1 (warp gw -> row gw) ----------------
    {
        while (ldacq(F_H1 + LCH) < (unsigned)HC) { }
        const float4* pr  = (const float4*)(c2e + (size_t)gw * HC);
        const float4* c1b = (const float4*)g_c1;
        float a = dot4(pr[lane],      __ldcg(c1b + lane))
                + dot4(pr[lane + 32], __ldcg(c1b + lane + 32));
        a = warp_sum(a);
        if (lane == 0) __stcg(&g_xc[gw], a);
        __syncthreads();
        if (threadIdx.x == 0) sign(F_XC, 8);
    }

    // ---------------- word LSTM layer 0 (warp gw -> element gw) ----------------
    const int e = gw;
    {
        while ((unsigned)(ldacq(F_XC)   <  512u) |
               (unsigned)(ldacq(F_GATE) <    1u) |
               (unsigned)(ldacq(F_WIHE) < 2048u) |
               (unsigned)(ldacq(F_HP0)  < 2048u)) { }
        const float gv = __ldcg(&g_gate);
        const float4* xc = (const float4*)g_xc;
        float4 xv[4];
#pragma unroll
        for (int u = 0; u < 4; u++) xv[u] = __ldcg(xc + lane + 32 * u);
        float acc[4];
#pragma unroll
        for (int q = 0; q < 4; q++) {
            const int row = q * HW + e;
            const float4* pwi = (const float4*)(word_Wih + (size_t)row * HW);
            float a = 0.f;
#pragma unroll
            for (int u = 0; u < 4; u++) a += dot4(__ldcg(pwi + lane + 32 * u), xv[u]);
            acc[q] = gv * warp_sum(a) + (1.f - gv) * __ldcg(&g_wihe[row]) + __ldcg(&g_hp[row]);
        }
        const float ig = fsig(acc[0]), fg = fsig(acc[1]);
        const float gg = ftanh(acc[2]), og = fsig(acc[3]);
        const float cw = fg * h_word_c[e] + ig * gg;
        const float hw = og * ftanh(cw);
        if (lane == 0) {
            __stcg(&g_wh[e], hw);
            out[OUT_WH + e] = hw;
            out[OUT_WC + e] = cw;
        }
        __syncthreads();
        if (threadIdx.x == 0) sign(F_W0, 8);
    }

    // ---------------- word LSTM layer 1 ----------------
    {
        while ((unsigned)(ldacq(F_HP1) < 2048u) |
               (unsigned)(ldacq(F_W0)  <  512u)) { }
        const float4* xb = (const float4*)g_wh;
        float4 xv[4];
#pragma unroll
        for (int u = 0; u < 4; u++) xv[u] = __ldcg(xb + lane + 32 * u);
        float acc[4];
#pragma unroll
        for (int q = 0; q < 4; q++) {
            const int row = 2048 + q * HW + e;
            const float4* pwi = (const float4*)(word_Wih + (size_t)row * HW);
            float a = 0.f;
#pragma unroll
            for (int u = 0; u < 4; u++) a += dot4(__ldcg(pwi + lane + 32 * u), xv[u]);
            acc[q] = warp_sum(a) + __ldcg(&g_hp[row]);
        }
        const float ig = fsig(acc[0]), fg = fsig(acc[1]);
        const float gg = ftanh(acc[2]), og = fsig(acc[3]);
        const float cw = fg * h_word_c[HW + e] + ig * gg;
        const float hw = og * ftanh(cw);
        if (lane == 0) {
            __stcg(&g_y[e], hw);
            out[OUT_WH + HW + e] = hw;
            out[OUT_WC + HW + e] = cw;
        }
    }
}

// ============ decoder GEMV (50000 x 512), 2 rows/warp, streaming loads ============
__global__ void __launch_bounds__(NTD) k_dec(const float* __restrict__ dec_W,
                                             const float* __restrict__ dec_b,
                                             float* __restrict__ out)
{
    // reset dataflow flags for the next graph replay (k_fused already done)
    if (blockIdx.x == 0) {
        for (int i = threadIdx.x; i < NFLAGS * 32; i += NTD) g_flags[i] = 0;
    }

    __shared__ float ys[HW];
    for (int i = threadIdx.x; i < HW; i += NTD) ys[i] = __ldcg(&g_y[i]);
    __syncthreads();

    const int lane = threadIdx.x & 31;
    const int wid  = threadIdx.x >> 5;
    const int gw   = blockIdx.x * (NTD / 32) + wid;
    const int r0   = 2 * gw;                        // 25000 warps * 2 rows

    const float4* y4 = (const float4*)ys;
    float4 yv[4];
#pragma unroll
    for (int u = 0; u < 4; u++) yv[u] = y4[lane + 32 * u];

    const float4* w0 = (const float4*)(dec_W + (size_t)r0 * HW);
    const float4* w1 = w0 + HW / 4;
    float a0 = 0.f, a1 = 0.f;
#pragma unroll
    for (int u = 0; u < 4; u++) {
        const float4 v0 = __ldcs(w0 + lane + 32 * u);   // evict-first: protect L2
        const float4 v1 = __ldcs(w1 + lane + 32 * u);
        a0 += dot4(v0, yv[u]);
        a1 += dot4(v1, yv[u]);
    }
    a0 = warp_sum(a0);
    a1 = warp_sum(a1);
    if (lane == 0) {
        out[r0]     = a0 + dec_b[r0];
        out[r0 + 1] = a1 + dec_b[r0 + 1];
    }
}

// ---------------- launch ----------------
extern "C" void kernel_launch(void* const* d_in, const int* in_sizes, int n_in,
                              void* d_out, int out_size)
{
    (void)in_sizes; (void)n_in; (void)out_size;
    const int*   x_word   = (const int*)  d_in[0];
    const int*   x_char   = (const int*)  d_in[1];
    const float* h_word_h = (const float*)d_in[2];
    const float* h_word_c = (const float*)d_in[3];
    const float* h_char_h = (const float*)d_in[4];
    const float* h_char_c = (const float*)d_in[5];
    const float* word_emb = (const float*)d_in[6];
    const float* word_Wih = (const float*)d_in[7];
    const float* word_Whh = (const float*)d_in[8];
    const float* word_bih = (const float*)d_in[9];
    const float* word_bhh = (const float*)d_in[10];
    const float* dec_W    = (const float*)d_in[11];
    const float* dec_b    = (const float*)d_in[12];
    const float* char_emb = (const float*)d_in[13];
    const float* char_Wih = (const float*)d_in[14];
    const float* char_Whh = (const float*)d_in[15];
    const float* char_bih = (const float*)d_in[16];
    const float* char_bhh = (const float*)d_in[17];
    const float* c2e      = (const float*)d_in[18];
    const float* g_w      = (const float*)d_in[19];
    const float* g_b      = (const float*)d_in[20];
    float* out = (float*)d_out;

    k_fused<<<NBF, NT1>>>(x_word, x_char, h_word_h, h_word_c, h_char_h, h_char_c,
                          word_emb, word_Wih, word_Whh, word_bih, word_bhh,
                          char_emb, char_Wih, char_Whh, char_bih, char_bhh,
                          c2e, g_w, g_b, out);
    k_dec<<<NBD, NTD>>>(dec_W, dec_b, out);
}

// round 8
// speedup vs baseline: 1.0852x; 1.0543x over previous
#include <cuda_runtime.h>
#include <math.h>
#include <stdint.h>

// ---------------- constants ----------------
#define NBF   148         // fused kernel blocks (1/SM, all co-resident)
#define NBC   64          // compute CTAs (512 warps)
#define NAUX  (NBF - NBC) // 84 aux CTAs
#define NT1   256
#define NBD   3125        // decoder: 3125 blocks * 8 warps * 2 rows = 50000
#define NTD   256

#define HC    256
#define HW    512
#define VOC   50000
#define LCH   12

// d_out layout: [y(50000) | h_word_h(1024) | h_word_c(1024) | h_char_h(512) | h_char_c(512)]
#define OUT_WH  50000
#define OUT_WC  51024
#define OUT_CH  52048
#define OUT_CC  52560

// ---------------- dataflow flags (one 128B line each) ----------------
#define F_H0    0     // +p : char layer0 state p complete (target 256)
#define F_H1    13    // +p : char layer1 state p complete (target 256)
#define F_PX    26    // +t : layer0 x-partials step t (target 1024, <=84 atomics)
#define F_XC    38    // xc rows (target 512)
#define F_GATE  39    // gate (target 1)
#define F_HP0   40    // word l0 h-partials (target 2048, <=84 atomics)
#define F_HP1   41    // word l1 h-partials (target 2048, <=84 atomics)
#define F_WIHE  42    // Wih_l0 . word_emb (target 2048, <=84 atomics)
#define F_W0    43    // word l0 elements (target 512)
#define NFLAGS  45
__device__ unsigned g_flags[NFLAGS * 32];

// ---------------- device-global scratch ----------------
__device__ float g_h0[4][HC];         // char layer0 state ring
__device__ float g_h1[4][HC];         // char layer1 state ring
__device__ float g_c1[HC];
__device__ float g_px[LCH * 1024];    // layer0: Wih@x_t + biases
__device__ float g_xc[HW];
__device__ float g_gate;
__device__ float g_wihe[2048];        // word l0: Wih@word_emb[widx]
__device__ float g_hp[2 * 2048];      // word: Whh@h_prev + biases
__device__ float g_wh[HW];
__device__ float g_y[HW];
__device__ float g_sink;

// ---------------- helpers ----------------
__device__ __forceinline__ void sign(int idx, unsigned n) {
    asm volatile("red.release.gpu.add.u32 [%0], %1;"
                 :: "l"(&g_flags[idx * 32]), "r"(n) : "memory");
}
__device__ __forceinline__ unsigned ldacq(int idx) {
    unsigned v;
    asm volatile("ld.acquire.gpu.u32 %0, [%1];"
                 : "=r"(v) : "l"(&g_flags[idx * 32]) : "memory");
    return v;
}
__device__ __forceinline__ float warp_sum(float v) {
#pragma unroll
    for (int o = 16; o > 0; o >>= 1) v += __shfl_xor_sync(0xffffffffu, v, o);
    return v;
}
__device__ __forceinline__ float fsig(float x)  { return __fdividef(1.f, 1.f + __expf(-x)); }
__device__ __forceinline__ float ftanh(float x) { float e = __expf(2.f * x); return 1.f - __fdividef(2.f, e + 1.f); }
__device__ __forceinline__ float dot4(float4 a, float4 b) {
    return a.x * b.x + a.y * b.y + a.z * b.z + a.w * b.w;
}
__device__ __forceinline__ int imax(int a, int b) { return a > b ? a : b; }
__device__ __forceinline__ int imin(int a, int b) { return a < b ? a : b; }

// ============ fused kernel ============
__global__ void __launch_bounds__(NT1, 1) k_fused(
    const int*   x_word,   const int*   x_char,
    const float* h_word_h, const float* h_word_c,
    const float* h_char_h, const float* h_char_c,
    const float* word_emb, const float* word_Wih, const float* word_Whh,
    const float* word_bih, const float* word_bhh,
    const float* char_emb, const float* char_Wih, const float* char_Whh,
    const float* char_bih, const float* char_bhh,
    const float* c2e,      const float* gw_vec,   const float* gb_scal,
    float* out)
{
    const int lane = threadIdx.x & 31;
    const int wid  = threadIdx.x >> 5;

    // ================= aux CTAs =================
    if (blockIdx.x >= NBC) {
        const int ab = blockIdx.x - NBC;            // 0..83

        __shared__ int sxa[LCH];
        if (threadIdx.x < LCH) sxa[threadIdx.x] = x_char[threadIdx.x];
        __syncthreads();

        // gate — CTA 83 (px-idle) warp 0, fully independent
        if (ab == 83 && wid == 0) {
            const int widx = x_word[0];
            const float4* we = (const float4*)(word_emb + (size_t)widx * HW);
            const float4* gp = (const float4*)gw_vec;
            float s = 0.f;
#pragma unroll
            for (int u = 0; u < 4; u++) s += dot4(gp[lane + 32 * u], we[lane + 32 * u]);
            s = warp_sum(s) + gb_scal[0];
            if (lane == 0) { __stcg(&g_gate, fmaxf(s, 0.f)); sign(F_GATE, 1); }
        }

        // ---- stage 1: px, CTA-chunked (13 rows/CTA), ONE aggregated sig per t ----
        {
            const int r0c = imin(ab * 13, 1024);
            const int r1c = imin(r0c + 13, 1024);
            for (int r = r0c + wid; r < r1c; r += 8) {
                const float4* w = (const float4*)(char_Wih + (size_t)r * HC);
                const float4 w0 = w[lane], w1 = w[lane + 32];
                const float  b  = char_bih[r] + char_bhh[r];
                float vals[LCH];
#pragma unroll
                for (int t = 0; t < LCH; t++) {
                    const float4* xe = (const float4*)(char_emb + (size_t)sxa[t] * HC);
                    vals[t] = dot4(w0, xe[lane]) + dot4(w1, xe[lane + 32]);
                }
#pragma unroll
                for (int t = 0; t < LCH; t++) {
                    const float a = warp_sum(vals[t]);
                    if (lane == 0) __stcg(&g_px[t * 1024 + r], a + b);
                }
            }
            __syncthreads();
            if (threadIdx.x == 0 && r1c > r0c) {
                const unsigned n = (unsigned)(r1c - r0c);
#pragma unroll
                for (int t = 0; t < LCH; t++) sign(F_PX + t, n);
            }
        }

        // ---- stage 2: wihe(2048) + hp0(2048) + hp1(2048), CTA-chunked ----
        {
            const int z0 = imin(ab * 74, 6144);
            const int z1 = imin(z0 + 74, 6144);
            const int widx = x_word[0];
            const float4* we = (const float4*)(word_emb + (size_t)widx * HW);
            float4 ev[4];
#pragma unroll
            for (int u = 0; u < 4; u++) ev[u] = we[lane + 32 * u];

            for (int z = z0 + wid; z < z1; z += 8) {
                if (z < 2048) {                          // wihe row z
                    const float4* w = (const float4*)(word_Wih + (size_t)z * HW);
                    float a = 0.f;
#pragma unroll
                    for (int u = 0; u < 4; u++) a += dot4(w[lane + 32 * u], ev[u]);
                    a = warp_sum(a);
                    if (lane == 0) __stcg(&g_wihe[z], a);
                } else if (z < 4096) {                   // hp layer0 row z-2048
                    const int rr = z - 2048;
                    const float4* w  = (const float4*)(word_Whh + (size_t)rr * HW);
                    const float4* hv = (const float4*)h_word_h;
                    float a = 0.f;
#pragma unroll
                    for (int u = 0; u < 4; u++) a += dot4(w[lane + 32 * u], hv[lane + 32 * u]);
                    a = warp_sum(a);
                    if (lane == 0) __stcg(&g_hp[rr], a + word_bih[rr] + word_bhh[rr]);
                } else {                                 // hp layer1 row z-4096 (+2048)
                    const int row = z - 2048;            // 2048..4095
                    const float4* w  = (const float4*)(word_Whh + (size_t)row * HW);
                    const float4* hv = (const float4*)(h_word_h + HW);
                    float a = 0.f;
#pragma unroll
                    for (int u = 0; u < 4; u++) a += dot4(w[lane + 32 * u], hv[lane + 32 * u]);
                    a = warp_sum(a);
                    if (lane == 0) __stcg(&g_hp[row], a + word_bih[row] + word_bhh[row]);
                }
            }
            __syncthreads();
            if (threadIdx.x == 0 && z1 > z0) {
                const int c0 = imax(0, imin(z1, 2048) - imin(z0, 2048));
                const int c1 = imax(0, imin(z1, 4096) - imax(z0, 2048));
                const int c2 = imax(0, z1 - imax(z0, 4096));
                if (c0) sign(F_WIHE, (unsigned)c0);
                if (c1) sign(F_HP0,  (unsigned)c1);
                if (c2) sign(F_HP1,  (unsigned)c2);
            }
        }

        // tiny warm: keep c2e resident for the xc phase
        {
            float s = 0.f;
            const float4* cb = (const float4*)c2e;
            for (int i = ab * NT1 + threadIdx.x; i < HW * HC / 4; i += NAUX * NT1) {
                const float4 v = __ldcg(cb + i);
                s += v.x + v.w;
            }
            if (s == 1.25e33f) g_sink = s;
        }
        return;
    }

    // ================= compute CTAs (0..63) =================
    const int gw    = blockIdx.x * (NT1 / 32) + wid;   // 0..511
    const int layer = (gw >= HC) ? 1 : 0;
    const int j     = layer ? (gw - HC) : gw;

    float c = h_char_c[layer * HC + j];

    // seed state 0 (CTA-aggregated signal)
    if (lane == 0) {
        const float h0v = h_char_h[layer * HC + j];
        if (layer == 0) __stcg(&g_h0[0][j], h0v);
        else            __stcg(&g_h1[0][j], h0v);
    }
    __syncthreads();
    if (threadIdx.x == 0) sign(layer == 0 ? (F_H0 + 0) : (F_H1 + 0), 8);

    if (layer == 0) {
        // ---- layer 0: Whh in regs; Wih@x+bias precomputed in px ----
        float4 wh[4][2];
#pragma unroll
        for (int q = 0; q < 4; q++) {
            const float4* ph = (const float4*)(char_Whh + (size_t)(q * HC + j) * HC);
            wh[q][0] = ph[lane];
            wh[q][1] = ph[lane + 32];
        }
#pragma unroll 1
        for (int t = 0; t < LCH; t++) {
            // fused poll: px[t], h0(t), WAR guard on ring (h1(t-3) when t>=4)
            const int      gf = (t >= 4) ? (F_H1 + t - 3) : F_H1;
            const unsigned gt = (t >= 4) ? (unsigned)HC : 0u;
            while ((unsigned)(ldacq(F_PX + t) < 1024u) |
                   (unsigned)(ldacq(F_H0 + t) < (unsigned)HC) |
                   (unsigned)(ldacq(gf) < gt)) { }
            float px[4];
#pragma unroll
            for (int q = 0; q < 4; q++) px[q] = __ldcg(&g_px[t * 1024 + q * HC + j]);
            const float4* hb = (const float4*)g_h0[t & 3];
            const float4 h0 = __ldcg(hb + lane), h1 = __ldcg(hb + lane + 32);
            float acc[4];
#pragma unroll
            for (int q = 0; q < 4; q++)
                acc[q] = warp_sum(dot4(wh[q][0], h0) + dot4(wh[q][1], h1)) + px[q];
            const float ig = fsig(acc[0]), fg = fsig(acc[1]);
            const float gg = ftanh(acc[2]), og = fsig(acc[3]);
            c = fg * c + ig * gg;
            const float h = og * ftanh(c);
            if (lane == 0) {
                __stcg(&g_h0[(t + 1) & 3][j], h);
                if (t == LCH - 1) { out[OUT_CH + j] = h; out[OUT_CC + j] = c; }
            }
            __syncthreads();
            if (threadIdx.x == 0) sign(F_H0 + t + 1, 8);
        }
    } else {
        // ---- layer 1: full Wih+Whh in regs ----
        float4 wi[4][2], wh[4][2];
        float  bias[4];
#pragma unroll
        for (int q = 0; q < 4; q++) {
            const int row = 4 * HC + q * HC + j;
            const float4* pi = (const float4*)(char_Wih + (size_t)row * HC);
            const float4* ph = (const float4*)(char_Whh + (size_t)row * HC);
            wi[q][0] = pi[lane];      wi[q][1] = pi[lane + 32];
            wh[q][0] = ph[lane];      wh[q][1] = ph[lane + 32];
            bias[q]  = char_bih[row] + char_bhh[row];
        }
#pragma unroll 1
        for (int t = 0; t < LCH; t++) {
            // fused poll: x = h0(t+1), own h1(t)
            while ((unsigned)(ldacq(F_H0 + t + 1) < (unsigned)HC) |
                   (unsigned)(ldacq(F_H1 + t)     < (unsigned)HC)) { }
            const float4* xb = (const float4*)g_h0[(t + 1) & 3];
            const float4* hb = (const float4*)g_h1[t & 3];
            const float4 x0 = __ldcg(xb + lane), x1 = __ldcg(xb + lane + 32);
            const float4 h0 = __ldcg(hb + lane), h1 = __ldcg(hb + lane + 32);
            float acc[4];
#pragma unroll
            for (int q = 0; q < 4; q++) {
                float a = dot4(wi[q][0], x0) + dot4(wi[q][1], x1)
                        + dot4(wh[q][0], h0) + dot4(wh[q][1], h1);
                acc[q] = warp_sum(a) + bias[q];
            }
            const float ig = fsig(acc[0]), fg = fsig(acc[1]);
            const float gg = ftanh(acc[2]), og = fsig(acc[3]);
            c = fg * c + ig * gg;
            const float h = og * ftanh(c);
            if (lane == 0) {
                __stcg(&g_h1[(t + 1) & 3][j], h);
                if (t == LCH - 1) {
                    __stcg(&g_c1[j], c);
                    out[OUT_CH + HC + j] = h;
                    out[OUT_CC + HC + j] = c;
                }
            }
            __syncthreads();
            if (threadIdx.x == 0) sign(F_H1 + t + 1, 8);
        }
    }

    // ---------------- xc = c2e @ c1 (warp gw -> row gw) ----------------
    {
        while (ldacq(F_H1 + LCH) < (unsigned)HC) { }
        const float4* pr  = (const float4*)(c2e + (size_t)gw * HC);
        const float4* c1b = (const float4*)g_c1;
        float a = dot4(pr[lane],      __ldcg(c1b + lane))
                + dot4(pr[lane + 32], __ldcg(c1b + lane + 32));
        a = warp_sum(a);
        if (lane == 0) __stcg(&g_xc[gw], a);
        __syncthreads();
        if (threadIdx.x == 0) sign(F_XC, 8);
    }

    // ---------------- word LSTM layer 0 (warp gw -> element gw) ----------------
    const int e = gw;
    {
        while ((unsigned)(ldacq(F_XC)   <  512u) |
               (unsigned)(ldacq(F_GATE) <    1u) |
               (unsigned)(ldacq(F_WIHE) < 2048u) |
               (unsigned)(ldacq(F_HP0)  < 2048u)) { }
        const float gv = __ldcg(&g_gate);
        const float4* xc = (const float4*)g_xc;
        float4 xv[4];
#pragma unroll
        for (int u = 0; u < 4; u++) xv[u] = __ldcg(xc + lane + 32 * u);
        float acc[4];
#pragma unroll
        for (int q = 0; q < 4; q++) {
            const int row = q * HW + e;
            const float4* pwi = (const float4*)(word_Wih + (size_t)row * HW);
            float a = 0.f;
#pragma unroll
            for (int u = 0; u < 4; u++) a += dot4(__ldcg(pwi + lane + 32 * u), xv[u]);
            acc[q] = gv * warp_sum(a) + (1.f - gv) * __ldcg(&g_wihe[row]) + __ldcg(&g_hp[row]);
        }
        const float ig = fsig(acc[0]), fg = fsig(acc[1]);
        const float gg = ftanh(acc[2]), og = fsig(acc[3]);
        const float cw = fg * h_word_c[e] + ig * gg;
        const float hw = og * ftanh(cw);
        if (lane == 0) {
            __stcg(&g_wh[e], hw);
            out[OUT_WH + e] = hw;
            out[OUT_WC + e] = cw;
        }
        __syncthreads();
        if (threadIdx.x == 0) sign(F_W0, 8);
    }

    // ---------------- word LSTM layer 1 ----------------
    {
        while ((unsigned)(ldacq(F_HP1) < 2048u) |
               (unsigned)(ldacq(F_W0)  <  512u)) { }
        const float4* xb = (const float4*)g_wh;
        float4 xv[4];
#pragma unroll
        for (int u = 0; u < 4; u++) xv[u] = __ldcg(xb + lane + 32 * u);
        float acc[4];
#pragma unroll
        for (int q = 0; q < 4; q++) {
            const int row = 2048 + q * HW + e;
            const float4* pwi = (const float4*)(word_Wih + (size_t)row * HW);
            float a = 0.f;
#pragma unroll
            for (int u = 0; u < 4; u++) a += dot4(__ldcg(pwi + lane + 32 * u), xv[u]);
            acc[q] = warp_sum(a) + __ldcg(&g_hp[row]);
        }
        const float ig = fsig(acc[0]), fg = fsig(acc[1]);
        const float gg = ftanh(acc[2]), og = fsig(acc[3]);
        const float cw = fg * h_word_c[HW + e] + ig * gg;
        const float hw = og * ftanh(cw);
        if (lane == 0) {
            __stcg(&g_y[e], hw);
            out[OUT_WH + HW + e] = hw;
            out[OUT_WC + HW + e] = cw;
        }
    }
}

// ============ decoder GEMV (50000 x 512), 2 rows/warp, streaming loads ============
__global__ void __launch_bounds__(NTD) k_dec(const float* __restrict__ dec_W,
                                             const float* __restrict__ dec_b,
                                             float* __restrict__ out)
{
    // reset dataflow flags for the next graph replay (k_fused already done)
    if (blockIdx.x == 0) {
        for (int i = threadIdx.x; i < NFLAGS * 32; i += NTD) g_flags[i] = 0;
    }

    __shared__ float ys[HW];
    for (int i = threadIdx.x; i < HW; i += NTD) ys[i] = __ldcg(&g_y[i]);
    __syncthreads();

    const int lane = threadIdx.x & 31;
    const int wid  = threadIdx.x >> 5;
    const int gw   = blockIdx.x * (NTD / 32) + wid;
    const int r0   = 2 * gw;                        // 25000 warps * 2 rows

    const float4* y4 = (const float4*)ys;
    float4 yv[4];
#pragma unroll
    for (int u = 0; u < 4; u++) yv[u] = y4[lane + 32 * u];

    const float4* w0 = (const float4*)(dec_W + (size_t)r0 * HW);
    const float4* w1 = w0 + HW / 4;
    float a0 = 0.f, a1 = 0.f;
#pragma unroll
    for (int u = 0; u < 4; u++) {
        const float4 v0 = __ldcs(w0 + lane + 32 * u);   // evict-first: protect L2
        const float4 v1 = __ldcs(w1 + lane + 32 * u);
        a0 += dot4(v0, yv[u]);
        a1 += dot4(v1, yv[u]);
    }
    a0 = warp_sum(a0);
    a1 = warp_sum(a1);
    if (lane == 0) {
        out[r0]     = a0 + dec_b[r0];
        out[r0 + 1] = a1 + dec_b[r0 + 1];
    }
}

// ---------------- launch ----------------
extern "C" void kernel_launch(void* const* d_in, const int* in_sizes, int n_in,
                              void* d_out, int out_size)
{
    (void)in_sizes; (void)n_in; (void)out_size;
    const int*   x_word   = (const int*)  d_in[0];
    const int*   x_char   = (const int*)  d_in[1];
    const float* h_word_h = (const float*)d_in[2];
    const float* h_word_c = (const float*)d_in[3];
    const float* h_char_h = (const float*)d_in[4];
    const float* h_char_c = (const float*)d_in[5];
    const float* word_emb = (const float*)d_in[6];
    const float* word_Wih = (const float*)d_in[7];
    const float* word_Whh = (const float*)d_in[8];
    const float* word_bih = (const float*)d_in[9];
    const float* word_bhh = (const float*)d_in[10];
    const float* dec_W    = (const float*)d_in[11];
    const float* dec_b    = (const float*)d_in[12];
    const float* char_emb = (const float*)d_in[13];
    const float* char_Wih = (const float*)d_in[14];
    const float* char_Whh = (const float*)d_in[15];
    const float* char_bih = (const float*)d_in[16];
    const float* char_bhh = (const float*)d_in[17];
    const float* c2e      = (const float*)d_in[18];
    const float* g_w      = (const float*)d_in[19];
    const float* g_b      = (const float*)d_in[20];
    float* out = (float*)d_out;

    k_fused<<<NBF, NT1>>>(x_word, x_char, h_word_h, h_word_c, h_char_h, h_char_c,
                          word_emb, word_Wih, word_Whh, word_bih, word_bhh,
                          char_emb, char_Wih, char_Whh, char_bih, char_bhh,
                          c2e, g_w, g_b, out);
    k_dec<<<NBD, NTD>>>(dec_W, dec_b, out);
}